// round 11
// baseline (speedup 1.0000x reference)
#include <cuda_runtime.h>
#include <cstdint>
#include <math.h>

#define NROWS   131072
#define DDIM    128
#define KCODES  1024
#define BM      128         // rows per CTA
#define NC      128         // codes per chunk
#define NCHUNKS (KCODES / NC)
#define PITCH   132         // smem row pitch (floats): frag LDS bank = lane -> conflict-free
#define TAU1    0.12f       // tf32 score-margin escalation threshold
#define TAU2    2e-3f       // fp32 dist-margin escalation threshold

// ---- device scratch (static; no allocation allowed) -----------------------
__device__ float g_ET[KCODES * DDIM];   // [K][D] row-major (bitwise copies of E)
__device__ float g_see[KCODES];         // ||e_k||^2
__device__ int   g_cnt;                 // stage-2 row count
__device__ int   g_rows[NROWS];
__device__ int   g_cnt2;                // stage-3 row count
__device__ int   g_rows2[NROWS];

__device__ __forceinline__ uint32_t f32_to_tf32(float f) {
    uint32_t o;
    asm("cvt.rn.tf32.f32 %0, %1;" : "=r"(o) : "f"(f));
    return o;
}
__device__ __forceinline__ void mma_tf32(float* c, const uint32_t* a,
                                         uint32_t b0, uint32_t b1) {
    asm volatile(
        "mma.sync.aligned.m16n8k8.row.col.f32.tf32.tf32.f32 "
        "{%0,%1,%2,%3}, {%4,%5,%6,%7}, {%8,%9}, {%0,%1,%2,%3};"
        : "+f"(c[0]), "+f"(c[1]), "+f"(c[2]), "+f"(c[3])
        : "r"(a[0]), "r"(a[1]), "r"(a[2]), "r"(a[3]), "r"(b0), "r"(b1));
}

// ---------------------------------------------------------------------------
__global__ void vq_prep_kernel(const float* __restrict__ E) {
    int tid    = blockIdx.x * blockDim.x + threadIdx.x;
    int stride = gridDim.x * blockDim.x;
    if (tid == 0) { g_cnt = 0; g_cnt2 = 0; }

    for (int i = tid; i < KCODES * DDIM; i += stride) {
        int d = i / KCODES;
        int k = i - d * KCODES;
        g_ET[k * DDIM + d] = E[i];
    }
    for (int k = tid; k < KCODES; k += stride) {
        float s = 0.f;
        for (int d = 0; d < DDIM; d++) {
            float v = E[d * KCODES + k];
            s = __fmaf_rn(v, v, s);
        }
        g_see[k] = s;
    }
}

// ---------------------------------------------------------------------------
// Stage 1: tf32 mma.sync GEMM, score = see - 2*x.e, top-2 argmin, gather.
// 8 warps: warp w -> rows (w&3)*32..+31, code half (w>>2)*64 of each chunk.
// ---------------------------------------------------------------------------
__global__ void __launch_bounds__(256, 1)
vq_tc_kernel(const float* __restrict__ X, float* __restrict__ out) {
    extern __shared__ float smem[];
    float* Xs    = smem;                    // [BM][PITCH] tf32 bits
    float* Es    = Xs + BM * PITCH;         // [NC][PITCH] tf32 bits
    float* see_s = Es + NC * PITCH;         // [NC]
    float* sb1   = see_s + NC;              // [BM]
    float* sb2   = sb1 + BM;                // [BM]
    int*   sid   = (int*)(sb2 + BM);        // [BM]
    int*   bidx_s = sid + BM;               // [BM]

    const int tid   = threadIdx.x;
    const int w     = tid >> 5;
    const int lane  = tid & 31;
    const int r     = lane >> 2;            // fragment groupID = t/4
    const int c     = lane & 3;             // t%4
    const int mrow0 = (w & 3) * 32;
    const int nhalf = w >> 2;
    const int ncol0 = nhalf * 64;
    const size_t base = (size_t)blockIdx.x * BM;

    // X tile -> tf32, row-major pitch 132.
    {
        const float4* X4 = (const float4*)X;
        for (int i = tid; i < BM * (DDIM / 4); i += 256) {
            int m = i >> 5, k4 = i & 31;
            float4 v = X4[(base + m) * (DDIM / 4) + k4];
            uint4 u = { f32_to_tf32(v.x), f32_to_tf32(v.y),
                        f32_to_tf32(v.z), f32_to_tf32(v.w) };
            *(uint4*)(Xs + m * PITCH + k4 * 4) = u;
        }
    }

    // Top-2 per row-slot. Slots: rows mrow0 + r + {0, 8, 16, 24}.
    float b1v[4], b2v[4];
    int   biv[4];
    #pragma unroll
    for (int i = 0; i < 4; i++) { b1v[i] = INFINITY; b2v[i] = INFINITY; biv[i] = 0; }

    const float4* ET4 = (const float4*)g_ET;

    for (int chunk = 0; chunk < NCHUNKS; chunk++) {
        __syncthreads();
        for (int i = tid; i < NC * (DDIM / 4); i += 256) {
            int n = i >> 5, k4 = i & 31;
            float4 v = ET4[(size_t)(chunk * NC + n) * (DDIM / 4) + k4];
            uint4 u = { f32_to_tf32(v.x), f32_to_tf32(v.y),
                        f32_to_tf32(v.z), f32_to_tf32(v.w) };
            *(uint4*)(Es + n * PITCH + k4 * 4) = u;
        }
        if (tid < NC) see_s[tid] = g_see[chunk * NC + tid];
        __syncthreads();

        float acc[2][8][4];
        #pragma unroll
        for (int mt = 0; mt < 2; mt++)
            #pragma unroll
            for (int nt = 0; nt < 8; nt++)
                #pragma unroll
                for (int i = 0; i < 4; i++) acc[mt][nt][i] = 0.f;

        #pragma unroll
        for (int s = 0; s < DDIM / 8; s++) {
            const int k0 = s * 8;
            uint32_t a[2][4];
            #pragma unroll
            for (int mt = 0; mt < 2; mt++) {
                const float* ap = Xs + (mrow0 + mt * 16 + r) * PITCH + k0 + c;
                a[mt][0] = __float_as_uint(ap[0]);
                a[mt][1] = __float_as_uint(ap[8 * PITCH]);
                a[mt][2] = __float_as_uint(ap[4]);
                a[mt][3] = __float_as_uint(ap[8 * PITCH + 4]);
            }
            #pragma unroll
            for (int nt = 0; nt < 8; nt++) {
                const float* bp = Es + (ncol0 + nt * 8 + r) * PITCH + k0 + c;
                uint32_t b0 = __float_as_uint(bp[0]);
                uint32_t b1 = __float_as_uint(bp[4]);
                mma_tf32(acc[0][nt], a[0], b0, b1);
                mma_tf32(acc[1][nt], a[1], b0, b1);
            }
        }

        // Epilogue: c-frag (row r / r+8, cols 2c / 2c+1). Ascending code order
        // per slot -> strict '<' keeps lowest index.
        #pragma unroll
        for (int nt = 0; nt < 8; nt++) {
            const int colL = ncol0 + nt * 8 + 2 * c;
            const float se0 = see_s[colL], se1 = see_s[colL + 1];
            const int code0 = chunk * NC + colL;
            #pragma unroll
            for (int mt = 0; mt < 2; mt++) {
                const int s0 = mt * 2;       // row r slot
                const int s1 = mt * 2 + 1;   // row r+8 slot
                float sc;
                sc = __fmaf_rn(-2.0f, acc[mt][nt][0], se0);
                if (sc < b1v[s0]) { b2v[s0] = b1v[s0]; b1v[s0] = sc; biv[s0] = code0; }
                else if (sc < b2v[s0]) b2v[s0] = sc;
                sc = __fmaf_rn(-2.0f, acc[mt][nt][1], se1);
                if (sc < b1v[s0]) { b2v[s0] = b1v[s0]; b1v[s0] = sc; biv[s0] = code0 + 1; }
                else if (sc < b2v[s0]) b2v[s0] = sc;
                sc = __fmaf_rn(-2.0f, acc[mt][nt][2], se0);
                if (sc < b1v[s1]) { b2v[s1] = b1v[s1]; b1v[s1] = sc; biv[s1] = code0; }
                else if (sc < b2v[s1]) b2v[s1] = sc;
                sc = __fmaf_rn(-2.0f, acc[mt][nt][3], se1);
                if (sc < b1v[s1]) { b2v[s1] = b1v[s1]; b1v[s1] = sc; biv[s1] = code0 + 1; }
                else if (sc < b2v[s1]) b2v[s1] = sc;
            }
        }
    }

    // Reduce across the 4 lanes (same r, different c) sharing each row.
    #pragma unroll
    for (int i = 0; i < 4; i++) {
        float b1 = b1v[i], b2 = b2v[i];
        int   bi = biv[i];
        #pragma unroll
        for (int off = 1; off < 4; off <<= 1) {
            float ob1 = __shfl_xor_sync(0xffffffffu, b1, off);
            float ob2 = __shfl_xor_sync(0xffffffffu, b2, off);
            int   obi = __shfl_xor_sync(0xffffffffu, bi, off);
            float nb2 = fminf(fmaxf(b1, ob1), fminf(b2, ob2));
            if (ob1 < b1 || (ob1 == b1 && obi < bi)) { b1 = ob1; bi = obi; }
            b2 = nb2;
        }
        b1v[i] = b1; b2v[i] = b2; biv[i] = bi;
    }

    // Merge the two code halves (warp w vs w+4 share rows).
    const int rowoff[4] = { r, r + 8, r + 16, r + 24 };
    if (nhalf == 1 && c == 0) {
        #pragma unroll
        for (int i = 0; i < 4; i++) {
            int row = mrow0 + rowoff[i];
            sb1[row] = b1v[i]; sb2[row] = b2v[i]; sid[row] = biv[i];
        }
    }
    __syncthreads();
    if (nhalf == 0 && c == 0) {
        #pragma unroll
        for (int i = 0; i < 4; i++) {
            int row = mrow0 + rowoff[i];
            float ob1 = sb1[row], ob2 = sb2[row];
            int   obi = sid[row];
            float b1 = b1v[i], b2 = b2v[i];
            int   bi = biv[i];
            float nb2 = fminf(fmaxf(b1, ob1), fminf(b2, ob2));
            if (ob1 < b1 || (ob1 == b1 && obi < bi)) { b1 = ob1; bi = obi; }
            b2 = nb2;
            bidx_s[row] = bi;
            if (b2 - b1 < TAU1) {
                int pos = atomicAdd(&g_cnt, 1);
                g_rows[pos] = (int)(base + row);
            }
        }
    }
    __syncthreads();

    // Gather winners (flagged rows corrected by later stages).
    float4* out4 = (float4*)out;
    for (int i = tid; i < BM * (DDIM / 4); i += 256) {
        int m = i >> 5, v = i & 31;
        out4[(base + m) * (DDIM / 4) + v] = ET4[(size_t)bidx_s[m] * (DDIM / 4) + v];
    }
}

// ---------------------------------------------------------------------------
// Stage 2: fp32 full rescan of flagged rows (dist = sum (x-e)^2).
// ---------------------------------------------------------------------------
__global__ void __launch_bounds__(128, 8)
vq_stage2_kernel(const float* __restrict__ X, float* __restrict__ out) {
    __shared__ float xs[DDIM];
    __shared__ float rb1[128], rb2[128];
    __shared__ int   rid[128];
    __shared__ int   wsh;
    const int t = threadIdx.x;
    const int cnt = g_cnt;

    for (int r = blockIdx.x; r < cnt; r += gridDim.x) {
        const int row = g_rows[r];
        xs[t] = X[(size_t)row * DDIM + t];
        __syncthreads();

        float b1 = INFINITY, b2 = INFINITY;
        int   bi = 0;
        for (int c = 0; c < KCODES / 128; c++) {
            int k = t + 128 * c;
            const float* e = &g_ET[k * DDIM];
            float s = 0.f;
            #pragma unroll 8
            for (int d = 0; d < DDIM; d++) {
                float diff = xs[d] - e[d];
                s = __fmaf_rn(diff, diff, s);
            }
            if (s < b1)      { b2 = b1; b1 = s; bi = k; }
            else if (s < b2) { b2 = s; }
        }
        rb1[t] = b1; rb2[t] = b2; rid[t] = bi;
        __syncthreads();
        for (int off = 64; off > 0; off >>= 1) {
            if (t < off) {
                float ob1 = rb1[t + off], ob2 = rb2[t + off];
                int   oid = rid[t + off];
                float nb2 = fminf(fmaxf(rb1[t], ob1), fminf(rb2[t], ob2));
                if (ob1 < rb1[t] || (ob1 == rb1[t] && oid < rid[t])) { rb1[t] = ob1; rid[t] = oid; }
                rb2[t] = nb2;
            }
            __syncthreads();
        }
        if (t == 0) {
            wsh = rid[0];
            if (rb2[0] - rb1[0] < TAU2) {
                int pos = atomicAdd(&g_cnt2, 1);
                g_rows2[pos] = row;
            }
        }
        __syncthreads();
        out[(size_t)row * DDIM + t] = g_ET[wsh * DDIM + t];
        __syncthreads();
    }
}

// ---------------------------------------------------------------------------
// Stage 3: fp64 exact argmin for still-ambiguous rows.
// ---------------------------------------------------------------------------
__global__ void __launch_bounds__(128, 4)
vq_stage3_kernel(const float* __restrict__ X, float* __restrict__ out) {
    __shared__ float  xs[DDIM];
    __shared__ double rd[128];
    __shared__ int    ri[128];
    __shared__ int    wsh;
    const int t = threadIdx.x;
    const int cnt = g_cnt2;

    for (int r = blockIdx.x; r < cnt; r += gridDim.x) {
        const int row = g_rows2[r];
        xs[t] = X[(size_t)row * DDIM + t];
        __syncthreads();

        double bd = INFINITY;
        int    bi = 0;
        for (int c = 0; c < KCODES / 128; c++) {
            int k = t + 128 * c;
            const float* e = &g_ET[k * DDIM];
            double s = 0.0;
            #pragma unroll 8
            for (int d = 0; d < DDIM; d++) {
                double diff = (double)xs[d] - (double)e[d];
                s = fma(diff, diff, s);
            }
            if (s < bd || (s == bd && k < bi)) { bd = s; bi = k; }
        }
        rd[t] = bd; ri[t] = bi;
        __syncthreads();
        for (int off = 64; off > 0; off >>= 1) {
            if (t < off) {
                double od = rd[t + off]; int oi = ri[t + off];
                if (od < rd[t] || (od == rd[t] && oi < ri[t])) { rd[t] = od; ri[t] = oi; }
            }
            __syncthreads();
        }
        if (t == 0) wsh = ri[0];
        __syncthreads();
        out[(size_t)row * DDIM + t] = g_ET[wsh * DDIM + t];
        __syncthreads();
    }
}

// ---------------------------------------------------------------------------
extern "C" void kernel_launch(void* const* d_in, const int* in_sizes, int n_in,
                              void* d_out, int out_size) {
    const float* X   = (const float*)d_in[0];   // [131072,128]
    const float* E   = (const float*)d_in[1];   // [128,1024]
    float*       out = (float*)d_out;

    vq_prep_kernel<<<64, 256>>>(E);

    const int smem_bytes = (BM * PITCH + NC * PITCH + NC + 2 * BM) * 4 + 2 * BM * 4;
    cudaFuncSetAttribute(vq_tc_kernel,
                         cudaFuncAttributeMaxDynamicSharedMemorySize, smem_bytes);
    vq_tc_kernel<<<NROWS / BM, 256, smem_bytes>>>(X, out);

    vq_stage2_kernel<<<1024, 128>>>(X, out);
    vq_stage3_kernel<<<64, 128>>>(X, out);
}